// round 14
// baseline (speedup 1.0000x reference)
#include <cuda_runtime.h>

#define GH 64
#define GW 64
#define NOBJ 16
#define FEAT 256
#define BATCH 4
#define DECAY 0.95f

#define NROWS (BATCH * GH * GW * NOBJ)   // 262144
#define ROW_OUT (FEAT + 2)               // 258 floats = 1032 B

// Warp = 4 consecutive rows (one aligned object quad within one cell).
// r0 = 4*warp: rows r0,r0+2 are even -> output base 16B-aligned -> STG.128;
// rows r0+1,r0+3 odd -> STG.64 pairs. All per-warp scalars are vectorized:
// positions (2x uniform LDG.128), occl (1x uniform LDG.128),
// conf/temp (lane-0 float4 each). Predicate computed redundantly in all lanes.
__global__ __launch_bounds__(256)
void smg_kernel(const float* __restrict__ grid_state,
                const float* __restrict__ grid_conf,
                const float* __restrict__ grid_temp,
                const float* __restrict__ obj_feat,
                const float* __restrict__ positions,
                const float* __restrict__ occl,
                float* __restrict__ out)
{
    const int lane  = threadIdx.x & 31;
    const int wglob = blockIdx.x * 8 + (threadIdx.x >> 5);
    const int r0    = wglob * 4;                 // multiple of 4
    const int cell  = r0 >> 4;
    const int gw    = cell & (GW - 1);
    const int gh    = (cell >> 6) & (GH - 1);
    const int b     = cell >> 12;
    const int o0    = r0 & (NOBJ - 1);           // multiple of 4
    const int bo0   = b * NOBJ + o0;             // multiple of 4

    // ---- Front-batched bulk loads: 8x LDG.128 (4 rows x 64 float4) ----
    const float4* gs = (const float4*)grid_state + (size_t)r0 * (FEAT / 4);
    float4 v[8];
    #pragma unroll
    for (int i = 0; i < 8; i++)
        v[i] = gs[lane + 32 * i];

    // ---- Warp-uniform scalar loads (aligned vector broadcasts) ----
    const float4 p01 = *(const float4*)(positions + 2 * bo0);      // px0,py0,px1,py1
    const float4 p23 = *(const float4*)(positions + 2 * bo0 + 4);  // px2,py2,px3,py3
    const float4 oc4 = *(const float4*)(occl + bo0);

    // ---- Predicate + alpha for the 4 rows, computed in all lanes ----
    float px[4] = { p01.x, p01.z, p23.x, p23.z };
    float py[4] = { p01.y, p01.w, p23.y, p23.w };
    float oc[4] = { oc4.x, oc4.y, oc4.z, oc4.w };
    float a[4];
    #pragma unroll
    for (int k = 0; k < 4; k++) {
        const int gwt = (int)fminf(fmaxf(px[k] * (float)(GW - 1), 0.0f), 63.0f);
        const int ght = (int)fminf(fmaxf(py[k] * (float)(GH - 1), 0.0f), 63.0f);
        a[k] = ((gwt == gw) && (ght == gh)) ? (oc[k] < 0.5f ? 0.8f : 0.3f) : 0.0f;
    }

    // ---- Lane 0: conf/temp for all 4 rows (aligned float4 loads) ----
    if (lane == 0) {
        const float4 c4 = *(const float4*)(grid_conf + r0);
        const float4 t4 = *(const float4*)(grid_temp + r0);
        const float cs[4] = { c4.x, c4.y, c4.z, c4.w };
        const float ts[4] = { t4.x, t4.y, t4.z, t4.w };
        #pragma unroll
        for (int k = 0; k < 4; k++) {
            float c  = cs[k];
            float tm = ts[k];
            if (a[k] != 0.0f) {
                const bool vis = oc[k] < 0.5f;
                c  = vis ? fminf(1.0f, c * 0.9f + 0.5f) : c * DECAY;
                tm += vis ? 1.0f : 0.5f;
            }
            *(float2*)(out + (size_t)(r0 + k) * ROW_OUT + FEAT) =
                make_float2(c * DECAY, tm);
        }
    }

    // ---- Feature blend (warp-uniform; taken by 64 of 65536 warps) ----
    #pragma unroll
    for (int k = 0; k < 4; k++) {
        if (a[k] != 0.0f) {
            const float4* of = (const float4*)(obj_feat + (size_t)(bo0 + k) * FEAT);
            const float ak = a[k], ia = 1.0f - ak;
            float4 f;
            f = of[lane];
            v[2*k].x = ak * f.x + ia * v[2*k].x;  v[2*k].y = ak * f.y + ia * v[2*k].y;
            v[2*k].z = ak * f.z + ia * v[2*k].z;  v[2*k].w = ak * f.w + ia * v[2*k].w;
            f = of[lane + 32];
            v[2*k+1].x = ak * f.x + ia * v[2*k+1].x;  v[2*k+1].y = ak * f.y + ia * v[2*k+1].y;
            v[2*k+1].z = ak * f.z + ia * v[2*k+1].z;  v[2*k+1].w = ak * f.w + ia * v[2*k+1].w;
        }
    }

    // ---- Stores: even rows STG.128, odd rows STG.64 pairs ----
    #pragma unroll
    for (int k = 0; k < 4; k += 2) {             // even rows r0+k
        float4* ov = (float4*)(out + (size_t)(r0 + k) * ROW_OUT);
        ov[lane]      = v[2*k];
        ov[lane + 32] = v[2*k + 1];
    }
    #pragma unroll
    for (int k = 1; k < 4; k += 2) {             // odd rows r0+k
        float* ov = out + (size_t)(r0 + k) * ROW_OUT;
        const float4 w0 = v[2*k], w1 = v[2*k + 1];
        *(float2*)(ov + 4 * lane)            = make_float2(w0.x, w0.y);
        *(float2*)(ov + 4 * lane + 2)        = make_float2(w0.z, w0.w);
        *(float2*)(ov + 4 * (lane + 32))     = make_float2(w1.x, w1.y);
        *(float2*)(ov + 4 * (lane + 32) + 2) = make_float2(w1.z, w1.w);
    }
}

extern "C" void kernel_launch(void* const* d_in, const int* in_sizes, int n_in,
                              void* d_out, int out_size)
{
    const float* grid_state = (const float*)d_in[0];
    const float* grid_conf  = (const float*)d_in[1];
    const float* grid_temp  = (const float*)d_in[2];
    const float* obj_feat   = (const float*)d_in[3];
    const float* positions  = (const float*)d_in[4];
    const float* occl       = (const float*)d_in[5];
    float* out = (float*)d_out;

    smg_kernel<<<NROWS / 32, 256>>>(grid_state, grid_conf, grid_temp,
                                    obj_feat, positions, occl, out);
}

// round 15
// speedup vs baseline: 1.0178x; 1.0178x over previous
#include <cuda_runtime.h>

#define GH 64
#define GW 64
#define NOBJ 16
#define FEAT 256
#define BATCH 4
#define DECAY 0.95f

#define NROWS (BATCH * GH * GW * NOBJ)   // 262144
#define ROW_OUT (FEAT + 2)               // 258 floats = 1032 B

// Warp = 2 consecutive rows = contiguous 2064 B output span = 129 aligned
// float4s. Row1's 8 B phase shift vs float4 grid is repaired with 4 lane
// shuffles, so EVERY global store is a dense aligned STG.128 and the
// (conf*DECAY, temporal) tail pairs ride inside the stream.
__global__ __launch_bounds__(256, 8)
void smg_kernel(const float* __restrict__ grid_state,
                const float* __restrict__ grid_conf,
                const float* __restrict__ grid_temp,
                const float* __restrict__ obj_feat,
                const float* __restrict__ positions,
                const float* __restrict__ occl,
                float* __restrict__ out)
{
    const int lane  = threadIdx.x & 31;
    const int wglob = blockIdx.x * 8 + (threadIdx.x >> 5);
    const int r0    = wglob * 2;                 // even row
    const int cell  = r0 >> 4;
    const int gw    = cell & (GW - 1);
    const int gh    = (cell >> 6) & (GH - 1);
    const int b     = cell >> 12;
    const int bo0   = b * NOBJ + (r0 & (NOBJ - 1));
    const int bo1   = bo0 + 1;

    // ---- Warp-uniform scalar loads (L1 broadcast) ----
    const float px0 = positions[2 * bo0], py0 = positions[2 * bo0 + 1];
    const float px1 = positions[2 * bo1], py1 = positions[2 * bo1 + 1];
    const float oc0 = occl[bo0],          oc1 = occl[bo1];

    // ---- Front-batched bulk loads: 4x LDG.128 (2 rows x 64 float4) ----
    const float4* gs = (const float4*)grid_state + (size_t)r0 * (FEAT / 4);
    float4 v[4];
    #pragma unroll
    for (int j = 0; j < 4; j++)
        v[j] = gs[lane + 32 * j];

    // ---- Predicate + alpha (computed uniformly in all lanes) ----
    const int gwt0 = (int)fminf(fmaxf(px0 * (float)(GW - 1), 0.0f), 63.0f);
    const int ght0 = (int)fminf(fmaxf(py0 * (float)(GH - 1), 0.0f), 63.0f);
    const int gwt1 = (int)fminf(fmaxf(px1 * (float)(GW - 1), 0.0f), 63.0f);
    const int ght1 = (int)fminf(fmaxf(py1 * (float)(GH - 1), 0.0f), 63.0f);
    const bool vis0 = oc0 < 0.5f, vis1 = oc1 < 0.5f;
    const float a0 = ((gwt0 == gw) && (ght0 == gh)) ? (vis0 ? 0.8f : 0.3f) : 0.0f;
    const float a1 = ((gwt1 == gw) && (ght1 == gh)) ? (vis1 ? 0.8f : 0.3f) : 0.0f;

    // ---- Lane 0: conf/temp for both rows (8B-aligned float2 loads) ----
    float c0d = 0.0f, t0f = 0.0f, c1d = 0.0f, t1f = 0.0f;
    if (lane == 0) {
        const float2 c2 = *(const float2*)(grid_conf + r0);
        const float2 t2 = *(const float2*)(grid_temp + r0);
        float c0 = c2.x, t0 = t2.x, c1 = c2.y, t1 = t2.y;
        if (a0 != 0.0f) {
            c0 = vis0 ? fminf(1.0f, c0 * 0.9f + 0.5f) : c0 * DECAY;
            t0 += vis0 ? 1.0f : 0.5f;
        }
        if (a1 != 0.0f) {
            c1 = vis1 ? fminf(1.0f, c1 * 0.9f + 0.5f) : c1 * DECAY;
            t1 += vis1 ? 1.0f : 0.5f;
        }
        c0d = c0 * DECAY; t0f = t0;
        c1d = c1 * DECAY; t1f = t1;
    }

    // ---- Feature blend (warp-uniform; taken by 64 of 131072 warps) ----
    if (a0 != 0.0f) {
        const float4* of = (const float4*)(obj_feat + (size_t)bo0 * FEAT);
        const float ia = 1.0f - a0;
        float4 f;
        f = of[lane];
        v[0].x = a0 * f.x + ia * v[0].x;  v[0].y = a0 * f.y + ia * v[0].y;
        v[0].z = a0 * f.z + ia * v[0].z;  v[0].w = a0 * f.w + ia * v[0].w;
        f = of[lane + 32];
        v[1].x = a0 * f.x + ia * v[1].x;  v[1].y = a0 * f.y + ia * v[1].y;
        v[1].z = a0 * f.z + ia * v[1].z;  v[1].w = a0 * f.w + ia * v[1].w;
    }
    if (a1 != 0.0f) {
        const float4* of = (const float4*)(obj_feat + (size_t)bo1 * FEAT);
        const float ia = 1.0f - a1;
        float4 f;
        f = of[lane];
        v[2].x = a1 * f.x + ia * v[2].x;  v[2].y = a1 * f.y + ia * v[2].y;
        v[2].z = a1 * f.z + ia * v[2].z;  v[2].w = a1 * f.w + ia * v[2].w;
        f = of[lane + 32];
        v[3].x = a1 * f.x + ia * v[3].x;  v[3].y = a1 * f.y + ia * v[3].y;
        v[3].z = a1 * f.z + ia * v[3].z;  v[3].w = a1 * f.w + ia * v[3].w;
    }

    // ---- Realign row1 by 2 floats via lane shuffles ----
    // Batch A word (m=65+lane, e=lane+1): {v2.z, v2.w, elem_e.x, elem_e.y};
    //   elem_e comes from lane e (v[2]) for e<32, from lane 0 (v[3]) for e=32.
    // Batch B word (m=97+lane, e=lane+33): {v3.z, v3.w, elem_e.x, elem_e.y};
    //   elem_e from lane e-32 (v[3]) for e<64, from lane 0 (tail pair) for e=64.
    const unsigned FM = 0xffffffffu;
    const int nxt = (lane + 1) & 31;
    const float sAx = (lane == 0) ? v[3].x : v[2].x;
    const float sAy = (lane == 0) ? v[3].y : v[2].y;
    const float sBx = (lane == 0) ? c1d     : v[3].x;
    const float sBy = (lane == 0) ? t1f     : v[3].y;
    const float xA = __shfl_sync(FM, sAx, nxt);
    const float yA = __shfl_sync(FM, sAy, nxt);
    const float xB = __shfl_sync(FM, sBx, nxt);
    const float yB = __shfl_sync(FM, sBy, nxt);

    // ---- Stores: 129 dense aligned STG.128 across the 2064 B span ----
    float4* base = (float4*)(out + (size_t)r0 * ROW_OUT);
    base[lane]       = v[0];
    base[lane + 32]  = v[1];
    if (lane == 0)
        base[64] = make_float4(c0d, t0f, v[2].x, v[2].y);
    base[65 + lane]  = make_float4(v[2].z, v[2].w, xA, yA);
    base[97 + lane]  = make_float4(v[3].z, v[3].w, xB, yB);
}

extern "C" void kernel_launch(void* const* d_in, const int* in_sizes, int n_in,
                              void* d_out, int out_size)
{
    const float* grid_state = (const float*)d_in[0];
    const float* grid_conf  = (const float*)d_in[1];
    const float* grid_temp  = (const float*)d_in[2];
    const float* obj_feat   = (const float*)d_in[3];
    const float* positions  = (const float*)d_in[4];
    const float* occl       = (const float*)d_in[5];
    float* out = (float*)d_out;

    smg_kernel<<<NROWS / 16, 256>>>(grid_state, grid_conf, grid_temp,
                                    obj_feat, positions, occl, out);
}

// round 16
// speedup vs baseline: 1.0273x; 1.0094x over previous
#include <cuda_runtime.h>

#define GH 64
#define GW 64
#define NOBJ 16
#define FEAT 256
#define BATCH 4
#define DECAY 0.95f

#define NROWS (BATCH * GH * GW * NOBJ)   // 262144
#define ROW_OUT (FEAT + 2)               // 258 floats = 1032 B

// Warp = 2 consecutive rows = contiguous 2064 B output span = 129 aligned
// float4s; row1's 8 B phase shift repaired with 4 lane shuffles so every
// global store is a dense aligned STG.128. This round: streaming cache
// hints (.cs) on the touch-once bulk streams (only change vs R14).
__global__ __launch_bounds__(256, 8)
void smg_kernel(const float* __restrict__ grid_state,
                const float* __restrict__ grid_conf,
                const float* __restrict__ grid_temp,
                const float* __restrict__ obj_feat,
                const float* __restrict__ positions,
                const float* __restrict__ occl,
                float* __restrict__ out)
{
    const int lane  = threadIdx.x & 31;
    const int wglob = blockIdx.x * 8 + (threadIdx.x >> 5);
    const int r0    = wglob * 2;                 // even row
    const int cell  = r0 >> 4;
    const int gw    = cell & (GW - 1);
    const int gh    = (cell >> 6) & (GH - 1);
    const int b     = cell >> 12;
    const int bo0   = b * NOBJ + (r0 & (NOBJ - 1));
    const int bo1   = bo0 + 1;

    // ---- Warp-uniform scalar loads (default policy: tiny, reused tables) ----
    const float px0 = positions[2 * bo0], py0 = positions[2 * bo0 + 1];
    const float px1 = positions[2 * bo1], py1 = positions[2 * bo1 + 1];
    const float oc0 = occl[bo0],          oc1 = occl[bo1];

    // ---- Front-batched bulk loads: 4x LDG.128.CS (touch-once stream) ----
    const float4* gs = (const float4*)grid_state + (size_t)r0 * (FEAT / 4);
    float4 v[4];
    #pragma unroll
    for (int j = 0; j < 4; j++)
        v[j] = __ldcs(&gs[lane + 32 * j]);

    // ---- Predicate + alpha (computed uniformly in all lanes) ----
    const int gwt0 = (int)fminf(fmaxf(px0 * (float)(GW - 1), 0.0f), 63.0f);
    const int ght0 = (int)fminf(fmaxf(py0 * (float)(GH - 1), 0.0f), 63.0f);
    const int gwt1 = (int)fminf(fmaxf(px1 * (float)(GW - 1), 0.0f), 63.0f);
    const int ght1 = (int)fminf(fmaxf(py1 * (float)(GH - 1), 0.0f), 63.0f);
    const bool vis0 = oc0 < 0.5f, vis1 = oc1 < 0.5f;
    const float a0 = ((gwt0 == gw) && (ght0 == gh)) ? (vis0 ? 0.8f : 0.3f) : 0.0f;
    const float a1 = ((gwt1 == gw) && (ght1 == gh)) ? (vis1 ? 0.8f : 0.3f) : 0.0f;

    // ---- Lane 0: conf/temp for both rows ----
    float c0d = 0.0f, t0f = 0.0f, c1d = 0.0f, t1f = 0.0f;
    if (lane == 0) {
        const float2 c2 = *(const float2*)(grid_conf + r0);
        const float2 t2 = *(const float2*)(grid_temp + r0);
        float c0 = c2.x, t0 = t2.x, c1 = c2.y, t1 = t2.y;
        if (a0 != 0.0f) {
            c0 = vis0 ? fminf(1.0f, c0 * 0.9f + 0.5f) : c0 * DECAY;
            t0 += vis0 ? 1.0f : 0.5f;
        }
        if (a1 != 0.0f) {
            c1 = vis1 ? fminf(1.0f, c1 * 0.9f + 0.5f) : c1 * DECAY;
            t1 += vis1 ? 1.0f : 0.5f;
        }
        c0d = c0 * DECAY; t0f = t0;
        c1d = c1 * DECAY; t1f = t1;
    }

    // ---- Feature blend (warp-uniform; taken by 64 of 131072 warps) ----
    if (a0 != 0.0f) {
        const float4* of = (const float4*)(obj_feat + (size_t)bo0 * FEAT);
        const float ia = 1.0f - a0;
        float4 f;
        f = of[lane];
        v[0].x = a0 * f.x + ia * v[0].x;  v[0].y = a0 * f.y + ia * v[0].y;
        v[0].z = a0 * f.z + ia * v[0].z;  v[0].w = a0 * f.w + ia * v[0].w;
        f = of[lane + 32];
        v[1].x = a0 * f.x + ia * v[1].x;  v[1].y = a0 * f.y + ia * v[1].y;
        v[1].z = a0 * f.z + ia * v[1].z;  v[1].w = a0 * f.w + ia * v[1].w;
    }
    if (a1 != 0.0f) {
        const float4* of = (const float4*)(obj_feat + (size_t)bo1 * FEAT);
        const float ia = 1.0f - a1;
        float4 f;
        f = of[lane];
        v[2].x = a1 * f.x + ia * v[2].x;  v[2].y = a1 * f.y + ia * v[2].y;
        v[2].z = a1 * f.z + ia * v[2].z;  v[2].w = a1 * f.w + ia * v[2].w;
        f = of[lane + 32];
        v[3].x = a1 * f.x + ia * v[3].x;  v[3].y = a1 * f.y + ia * v[3].y;
        v[3].z = a1 * f.z + ia * v[3].z;  v[3].w = a1 * f.w + ia * v[3].w;
    }

    // ---- Realign row1 by 2 floats via lane shuffles ----
    const unsigned FM = 0xffffffffu;
    const int nxt = (lane + 1) & 31;
    const float sAx = (lane == 0) ? v[3].x : v[2].x;
    const float sAy = (lane == 0) ? v[3].y : v[2].y;
    const float sBx = (lane == 0) ? c1d     : v[3].x;
    const float sBy = (lane == 0) ? t1f     : v[3].y;
    const float xA = __shfl_sync(FM, sAx, nxt);
    const float yA = __shfl_sync(FM, sAy, nxt);
    const float xB = __shfl_sync(FM, sBx, nxt);
    const float yB = __shfl_sync(FM, sBy, nxt);

    // ---- Stores: 129 dense aligned STG.128.CS across the 2064 B span ----
    float4* base = (float4*)(out + (size_t)r0 * ROW_OUT);
    __stcs(&base[lane],      v[0]);
    __stcs(&base[lane + 32], v[1]);
    if (lane == 0)
        __stcs(&base[64], make_float4(c0d, t0f, v[2].x, v[2].y));
    __stcs(&base[65 + lane], make_float4(v[2].z, v[2].w, xA, yA));
    __stcs(&base[97 + lane], make_float4(v[3].z, v[3].w, xB, yB));
}

extern "C" void kernel_launch(void* const* d_in, const int* in_sizes, int n_in,
                              void* d_out, int out_size)
{
    const float* grid_state = (const float*)d_in[0];
    const float* grid_conf  = (const float*)d_in[1];
    const float* grid_temp  = (const float*)d_in[2];
    const float* obj_feat   = (const float*)d_in[3];
    const float* positions  = (const float*)d_in[4];
    const float* occl       = (const float*)d_in[5];
    float* out = (float*)d_out;

    smg_kernel<<<NROWS / 16, 256>>>(grid_state, grid_conf, grid_temp,
                                    obj_feat, positions, occl, out);
}